// round 11
// baseline (speedup 1.0000x reference)
#include <cuda_runtime.h>
#include <cstdint>

// Problem constants
#define TT    10
#define NH    12
#define DH    32
#define DIM   384
#define NB    16384
#define MROWS (NB * TT)        // 163840
#define NQKV  1152
#define KDIM  384
#define BK    32
#define NCHUNK (KDIM / BK)     // 12

// Scratch (device globals — allocation-free per harness rules)
__device__ float    g_qkv[(size_t)MROWS * NQKV];   // [163840, 1152]
__device__ float    g_att[(size_t)MROWS * DIM];    // [163840, 384]
__device__ uint32_t g_wq[NQKV * KDIM];             // qkv_w pre-converted to tf32 bits
__device__ uint32_t g_wp[DIM * KDIM];              // proj_w pre-converted to tf32 bits

__device__ __forceinline__ uint32_t f2tf(float x) {
    uint32_t r;
    asm("cvt.rna.tf32.f32 %0, %1;" : "=r"(r) : "f"(x));
    return r;
}

__device__ __forceinline__ uint32_t smem_u32(const void* p) {
    uint32_t a;
    asm("{ .reg .u64 t; cvta.to.shared.u64 t, %1; cvt.u32.u64 %0, t; }"
        : "=r"(a) : "l"(p));
    return a;
}

__device__ __forceinline__ void cp16(uint32_t dst, const void* src) {
    asm volatile("cp.async.cg.shared.global [%0], [%1], 16;"
                 :: "r"(dst), "l"(src) : "memory");
}
#define CP_COMMIT()  asm volatile("cp.async.commit_group;" ::: "memory")
#define CP_WAIT(n)   asm volatile("cp.async.wait_group %0;" :: "n"(n) : "memory")

__device__ __forceinline__ void mma_16x8x8(float* c, const uint32_t* a, const uint32_t* b) {
    asm volatile(
        "mma.sync.aligned.m16n8k8.row.col.f32.tf32.tf32.f32 "
        "{%0,%1,%2,%3}, {%4,%5,%6,%7}, {%8,%9}, {%0,%1,%2,%3};"
        : "+f"(c[0]), "+f"(c[1]), "+f"(c[2]), "+f"(c[3])
        : "r"(a[0]), "r"(a[1]), "r"(a[2]), "r"(a[3]),
          "r"(b[0]), "r"(b[1]));
}

// Tiny pre-pass: convert both weight matrices to tf32 (RNA) bit patterns.
__global__ void __launch_bounds__(256)
conv_w(const float* __restrict__ wq, const float* __restrict__ wp)
{
    const int nq = NQKV * KDIM / 4;   // 110592 float4
    const int np = DIM * KDIM / 4;    //  36864 float4
    int i = blockIdx.x * 256 + threadIdx.x;
    if (i < nq) {
        float4 v = reinterpret_cast<const float4*>(wq)[i];
        reinterpret_cast<uint4*>(g_wq)[i] =
            make_uint4(f2tf(v.x), f2tf(v.y), f2tf(v.z), f2tf(v.w));
    } else if (i < nq + np) {
        int j = i - nq;
        float4 v = reinterpret_cast<const float4*>(wp)[j];
        reinterpret_cast<uint4*>(g_wp)[j] =
            make_uint4(f2tf(v.x), f2tf(v.y), f2tf(v.z), f2tf(v.w));
    }
}

// ======================= TF32 GEMM, cp.async double-buffered =======================
// C[M,N] = A[M,K] * Btf[N,K]^T + bias[N]
//   A: raw fp32 row-major (cvt.rna applied per A-fragment after LDS)
//   Btf: tf32 bit patterns, row-major [N, K]
// CTA tile 128x128, BK=32, 4 warps (2x2), warp tile 64x64 (mfrag=4, nfrag=8).
// Dynamic smem: 2 stages x (A 18KB + B 18KB) = 72 KB, padded stride 36 words.
#define STAGE_BYTES 36864u          // 2 * 128 * 36 * 4
#define AB_BYTES    18432u          // 128 * 36 * 4

__global__ void __launch_bounds__(128, 2)
gemm_tf32(const float* __restrict__ A, const uint32_t* __restrict__ Btf,
          const float* __restrict__ bias, float* __restrict__ C, int N)
{
    extern __shared__ uint32_t dyn[];
    const uint32_t smem_base = smem_u32(dyn);

    const int tid  = threadIdx.x;
    const int warp = tid >> 5;
    const int lane = tid & 31;
    const int lq   = lane >> 2;          // 0..7
    const int lr   = lane & 3;           // 0..3
    const int wm   = (warp >> 1) * 64;   // warp row offset in CTA tile
    const int wn   = (warp & 1) * 64;    // warp col offset in CTA tile
    const size_t mblk = (size_t)blockIdx.y * 128;
    const int    nblk = blockIdx.x * 128;

    // Per-thread fill coordinates (8 x 16B per tile per chunk)
    const int frow = tid >> 3;           // base row 0..15 pattern: idx>>3 below
    (void)frow;

    float acc[4][8][4];
    #pragma unroll
    for (int i = 0; i < 4; i++)
        #pragma unroll
        for (int j = 0; j < 8; j++)
            #pragma unroll
            for (int r = 0; r < 4; r++)
                acc[i][j][r] = 0.0f;

    // ---- prefetch helper (inlined manually) ----
    auto prefetch = [&](int stage, int c) {
        const uint32_t aBase = smem_base + (uint32_t)stage * STAGE_BYTES;
        const uint32_t bBase = aBase + AB_BYTES;
        const int kb = c * BK;
        #pragma unroll
        for (int i = 0; i < 8; i++) {
            int idx = tid + i * 128;         // 0..1023
            int row = idx >> 3;              // 0..127
            int kc  = (idx & 7) << 2;        // 0,4,...,28
            uint32_t off = (uint32_t)(row * 36 + kc) * 4u;
            cp16(aBase + off, A + (mblk + row) * KDIM + kb + kc);
            cp16(bBase + off, Btf + (size_t)(nblk + row) * KDIM + kb + kc);
        }
        CP_COMMIT();
    };

    prefetch(0, 0);
    prefetch(1, 1);

    for (int c = 0; c < NCHUNK; c++) {
        const int s = c & 1;
        if (c < NCHUNK - 1) { CP_WAIT(1); } else { CP_WAIT(0); }
        __syncthreads();

        const uint32_t* As = dyn + (size_t)s * (STAGE_BYTES / 4);
        const uint32_t* Bs = As + (AB_BYTES / 4);

        #pragma unroll
        for (int ks = 0; ks < 4; ks++) {
            const int k0 = ks * 8;
            uint32_t af[4][4], bf[8][2];
            #pragma unroll
            for (int mf = 0; mf < 4; mf++) {
                const uint32_t* ar0 = As + (wm + mf * 16 + lq) * 36 + k0;
                const uint32_t* ar1 = ar0 + 8 * 36;
                af[mf][0] = f2tf(__uint_as_float(ar0[lr]));
                af[mf][1] = f2tf(__uint_as_float(ar1[lr]));
                af[mf][2] = f2tf(__uint_as_float(ar0[lr + 4]));
                af[mf][3] = f2tf(__uint_as_float(ar1[lr + 4]));
            }
            #pragma unroll
            for (int nf = 0; nf < 8; nf++) {
                const uint32_t* br = Bs + (wn + nf * 8 + lq) * 36 + k0;
                bf[nf][0] = br[lr];
                bf[nf][1] = br[lr + 4];
            }
            #pragma unroll
            for (int mf = 0; mf < 4; mf++)
                #pragma unroll
                for (int nf = 0; nf < 8; nf++)
                    mma_16x8x8(acc[mf][nf], af[mf], bf[nf]);
        }
        __syncthreads();

        if (c + 2 < NCHUNK) prefetch(s, c + 2);
    }

    // Epilogue: bias add + float2 stores
    #pragma unroll
    for (int mf = 0; mf < 4; mf++) {
        size_t row = mblk + wm + mf * 16 + lq;
        #pragma unroll
        for (int nf = 0; nf < 8; nf++) {
            int col = nblk + wn + nf * 8 + lr * 2;
            float b0 = __ldg(bias + col);
            float b1 = __ldg(bias + col + 1);
            float2 v0 = make_float2(acc[mf][nf][0] + b0, acc[mf][nf][1] + b1);
            float2 v1 = make_float2(acc[mf][nf][2] + b0, acc[mf][nf][3] + b1);
            *reinterpret_cast<float2*>(C + row * (size_t)N + col)       = v0;
            *reinterpret_cast<float2*>(C + (row + 8) * (size_t)N + col) = v1;
        }
    }
}

// ======================= fused attention (proven, unchanged) =======================
__global__ void __launch_bounds__(128)
attn_kernel(const float* __restrict__ bias_table)
{
    __shared__ float sQ[4][TT][33];
    __shared__ float sK[4][TT][33];
    __shared__ float sV[4][TT][33];
    __shared__ float sP[4][TT * TT];
    __shared__ float sB[(2 * TT - 1) * NH];

    const int w    = threadIdx.x >> 5;
    const int lane = threadIdx.x & 31;

    for (int i = threadIdx.x; i < (2 * TT - 1) * NH; i += 128)
        sB[i] = bias_table[i];

    const int unit = blockIdx.x * 4 + w;
    const int b = unit / NH;
    const int h = unit - b * NH;

    const float* base = g_qkv + (size_t)(b * TT) * NQKV + h * DH;

    __syncthreads();

    #pragma unroll
    for (int t = 0; t < TT; t++) {
        sQ[w][t][lane] = base[t * NQKV + lane];
        sK[w][t][lane] = base[t * NQKV + DIM + lane];
        sV[w][t][lane] = base[t * NQKV + 2 * DIM + lane];
    }
    __syncwarp();

    const float scale = 0.17677669529663687f;
    for (int e = lane; e < TT * TT; e += 32) {
        int t = e / TT;
        int j = e - t * TT;
        float a = 0.0f;
        #pragma unroll
        for (int d = 0; d < DH; d++)
            a += sQ[w][t][d] * sK[w][j][d];
        sP[w][e] = a * scale + sB[(t - j + TT - 1) * NH + h];
    }
    __syncwarp();

    if (lane < TT) {
        float row[TT];
        float m = -1e30f;
        #pragma unroll
        for (int j = 0; j < TT; j++) { row[j] = sP[w][lane * TT + j]; m = fmaxf(m, row[j]); }
        float s = 0.0f;
        #pragma unroll
        for (int j = 0; j < TT; j++) { row[j] = __expf(row[j] - m); s += row[j]; }
        float inv = 1.0f / s;
        #pragma unroll
        for (int j = 0; j < TT; j++) sP[w][lane * TT + j] = row[j] * inv;
    }
    __syncwarp();

    float* outp = g_att + (size_t)(b * TT) * DIM + h * DH;
    #pragma unroll
    for (int t = 0; t < TT; t++) {
        float a = 0.0f;
        #pragma unroll
        for (int j = 0; j < TT; j++)
            a += sP[w][t * TT + j] * sV[w][j][lane];
        outp[t * DIM + lane] = a;
    }
}

extern "C" void kernel_launch(void* const* d_in, const int* in_sizes, int n_in,
                              void* d_out, int out_size)
{
    (void)in_sizes; (void)n_in; (void)out_size;
    const float* x      = (const float*)d_in[0];   // [16384,10,384]
    const float* qkv_w  = (const float*)d_in[1];   // [1152,384]
    const float* qkv_b  = (const float*)d_in[2];   // [1152]
    const float* proj_w = (const float*)d_in[3];   // [384,384]
    const float* proj_b = (const float*)d_in[4];   // [384]
    const float* bias_t = (const float*)d_in[5];   // [19,12]
    float* out = (float*)d_out;                    // [163840,384]

    void* pq = nullptr; void* pa = nullptr;
    void* pwq = nullptr; void* pwp = nullptr;
    cudaGetSymbolAddress(&pq, g_qkv);
    cudaGetSymbolAddress(&pa, g_att);
    cudaGetSymbolAddress(&pwq, g_wq);
    cudaGetSymbolAddress(&pwp, g_wp);

    const int smem_bytes = 2 * (int)STAGE_BYTES;   // 73728
    cudaFuncSetAttribute(gemm_tf32, cudaFuncAttributeMaxDynamicSharedMemorySize, smem_bytes);

    // 0) Pre-convert weights to tf32 bits (~5 us)
    const int nconv = (NQKV * KDIM + DIM * KDIM) / 4;   // 147456 float4
    conv_w<<<(nconv + 255) / 256, 256>>>(qkv_w, proj_w);

    // 1) qkv = x @ qkv_w^T + qkv_b
    dim3 g1(NQKV / 128, MROWS / 128);   // (9, 1280)
    gemm_tf32<<<g1, 128, smem_bytes>>>(x, (const uint32_t*)pwq, qkv_b, (float*)pq, NQKV);

    // 2) attention, one warp per (b, h)
    attn_kernel<<<(NB * NH) / 4, 128>>>(bias_t);

    // 3) out = att @ proj_w^T + proj_b
    dim3 g2(DIM / 128, MROWS / 128);    // (3, 1280)
    gemm_tf32<<<g2, 128, smem_bytes>>>((const float*)pa, (const uint32_t*)pwp, proj_b, out, DIM);
}

// round 12
// speedup vs baseline: 1.0556x; 1.0556x over previous
#include <cuda_runtime.h>
#include <cstdint>

// Problem constants
#define TT    10
#define NH    12
#define DH    32
#define DIM   384
#define NB    16384
#define MROWS (NB * TT)        // 163840
#define NQKV  1152
#define KDIM  384
#define BK    32
#define NCHUNK (KDIM / BK)     // 12
#define NSTAGE 3

// Scratch (device globals — allocation-free per harness rules)
__device__ float    g_qkv[(size_t)MROWS * NQKV];   // [163840, 1152]
__device__ float    g_att[(size_t)MROWS * DIM];    // [163840, 384] (tf32 bits)
__device__ uint32_t g_wq[NQKV * KDIM];             // qkv_w tf32 bits
__device__ uint32_t g_wp[DIM * KDIM];              // proj_w tf32 bits

__device__ __forceinline__ uint32_t f2tf(float x) {
    uint32_t r;
    asm("cvt.rna.tf32.f32 %0, %1;" : "=r"(r) : "f"(x));
    return r;
}

__device__ __forceinline__ uint32_t smem_u32(const void* p) {
    uint32_t a;
    asm("{ .reg .u64 t; cvta.to.shared.u64 t, %1; cvt.u32.u64 %0, t; }"
        : "=r"(a) : "l"(p));
    return a;
}

__device__ __forceinline__ void cp16(uint32_t dst, const void* src) {
    asm volatile("cp.async.cg.shared.global [%0], [%1], 16;"
                 :: "r"(dst), "l"(src) : "memory");
}
#define CP_COMMIT()  asm volatile("cp.async.commit_group;" ::: "memory")
#define CP_WAIT(n)   asm volatile("cp.async.wait_group %0;" :: "n"(n) : "memory")

#define LDSM4(r0, r1, r2, r3, addr) \
    asm volatile("ldmatrix.sync.aligned.m8n8.x4.shared.b16 {%0,%1,%2,%3}, [%4];" \
                 : "=r"(r0), "=r"(r1), "=r"(r2), "=r"(r3) : "r"(addr))

__device__ __forceinline__ void mma_16x8x8(float* c, const uint32_t* a, const uint32_t* b) {
    asm volatile(
        "mma.sync.aligned.m16n8k8.row.col.f32.tf32.tf32.f32 "
        "{%0,%1,%2,%3}, {%4,%5,%6,%7}, {%8,%9}, {%0,%1,%2,%3};"
        : "+f"(c[0]), "+f"(c[1]), "+f"(c[2]), "+f"(c[3])
        : "r"(a[0]), "r"(a[1]), "r"(a[2]), "r"(a[3]),
          "r"(b[0]), "r"(b[1]));
}

// Pre-pass: convert both weight matrices to tf32 (RNA) bit patterns.
__global__ void __launch_bounds__(256)
conv_w(const float* __restrict__ wq, const float* __restrict__ wp)
{
    const int nq = NQKV * KDIM / 4;
    const int np = DIM * KDIM / 4;
    int i = blockIdx.x * 256 + threadIdx.x;
    if (i < nq) {
        float4 v = reinterpret_cast<const float4*>(wq)[i];
        reinterpret_cast<uint4*>(g_wq)[i] =
            make_uint4(f2tf(v.x), f2tf(v.y), f2tf(v.z), f2tf(v.w));
    } else if (i < nq + np) {
        int j = i - nq;
        float4 v = reinterpret_cast<const float4*>(wp)[j];
        reinterpret_cast<uint4*>(g_wp)[j] =
            make_uint4(f2tf(v.x), f2tf(v.y), f2tf(v.z), f2tf(v.w));
    }
}

// ======================= TF32 GEMM: ldmatrix + cp.async 3-stage =======================
// C[M,N] = A[M,K] * Btf[N,K]^T + bias[N]
//   CVT_A: apply cvt.rna to A fragments after LDSM (A stored as raw fp32).
//   Btf: tf32 bit patterns row-major [N, K].
// CTA tile 128x128, BK=32, 4 warps (2x2), warp tile 64x64. Row stride 36 words (144B).
#define STAGE_BYTES 36864u          // (128*36*4) * 2  (A half + B half)
#define AB_BYTES    18432u          // 128 * 36 * 4
#define ROWB        144u            // bytes per smem row

template<bool CVT_A>
__global__ void __launch_bounds__(128, 2)
gemm_tf32(const float* __restrict__ A, const uint32_t* __restrict__ Btf,
          const float* __restrict__ bias, float* __restrict__ C, int N)
{
    extern __shared__ uint32_t dyn[];
    const uint32_t smem_base = smem_u32(dyn);

    const int tid  = threadIdx.x;
    const int warp = tid >> 5;
    const int lane = tid & 31;
    const int lq   = lane >> 2;
    const int lr   = lane & 3;
    const int wm   = (warp >> 1) * 64;
    const int wn   = (warp & 1) * 64;
    const size_t mblk = (size_t)blockIdx.y * 128;
    const int    nblk = blockIdx.x * 128;

    // ldmatrix per-lane address offsets (bytes)
    //  A tile (16 rows x 8 k): lanes 0-15 -> rows 0-15, lanes 16-31 same rows +16B (k 4-7)
    const uint32_t a_off = (uint32_t)(lane & 15) * ROWB + (uint32_t)(lane >> 4) * 16u;
    //  B pair (2 nf tiles): lanes 0-15 -> rows 0-7 (+k half), lanes 16-31 -> rows 8-15
    const uint32_t b_off = ((uint32_t)(lane & 7) + (uint32_t)((lane >> 4) << 3)) * ROWB
                         + (uint32_t)(((lane >> 3) & 1) << 4);

    float acc[4][8][4];
    #pragma unroll
    for (int i = 0; i < 4; i++)
        #pragma unroll
        for (int j = 0; j < 8; j++)
            #pragma unroll
            for (int r = 0; r < 4; r++)
                acc[i][j][r] = 0.0f;

    auto prefetch = [&](int stage, int c) {
        const uint32_t aBase = smem_base + (uint32_t)stage * STAGE_BYTES;
        const uint32_t bBase = aBase + AB_BYTES;
        const int kb = c * BK;
        #pragma unroll
        for (int i = 0; i < 8; i++) {
            int idx = tid + i * 128;
            int row = idx >> 3;
            int kc  = (idx & 7) << 2;
            uint32_t off = (uint32_t)row * ROWB + (uint32_t)kc * 4u;
            cp16(aBase + off, A + (mblk + row) * KDIM + kb + kc);
            cp16(bBase + off, Btf + (size_t)(nblk + row) * KDIM + kb + kc);
        }
        CP_COMMIT();
    };

    prefetch(0, 0);
    prefetch(1, 1);

    int s = 0;
    for (int c = 0; c < NCHUNK; c++) {
        if (c < NCHUNK - 1) { CP_WAIT(1); } else { CP_WAIT(0); }
        __syncthreads();

        if (c + 2 < NCHUNK) {
            int ps = s + 2; if (ps >= NSTAGE) ps -= NSTAGE;
            prefetch(ps, c + 2);
        }

        const uint32_t aStage = smem_base + (uint32_t)s * STAGE_BYTES;
        const uint32_t aAddr0 = aStage + (uint32_t)wm * ROWB + a_off;
        const uint32_t bAddr0 = aStage + AB_BYTES + (uint32_t)wn * ROWB + b_off;

        #pragma unroll
        for (int ks = 0; ks < 4; ks++) {
            const uint32_t k0b = (uint32_t)ks * 32u;
            uint32_t af[4][4], bf[8][2];
            #pragma unroll
            for (int mf = 0; mf < 4; mf++) {
                LDSM4(af[mf][0], af[mf][1], af[mf][2], af[mf][3],
                      aAddr0 + (uint32_t)mf * (16u * ROWB) + k0b);
            }
            #pragma unroll
            for (int p = 0; p < 4; p++) {
                LDSM4(bf[2*p][0], bf[2*p][1], bf[2*p+1][0], bf[2*p+1][1],
                      bAddr0 + (uint32_t)p * (16u * ROWB) + k0b);
            }
            if (CVT_A) {
                #pragma unroll
                for (int mf = 0; mf < 4; mf++)
                    #pragma unroll
                    for (int r = 0; r < 4; r++)
                        af[mf][r] = f2tf(__uint_as_float(af[mf][r]));
            }
            #pragma unroll
            for (int mf = 0; mf < 4; mf++)
                #pragma unroll
                for (int nf = 0; nf < 8; nf++)
                    mma_16x8x8(acc[mf][nf], af[mf], bf[nf]);
        }

        if (++s >= NSTAGE) s -= NSTAGE;
    }

    // Epilogue: bias add + float2 stores
    #pragma unroll
    for (int mf = 0; mf < 4; mf++) {
        size_t row = mblk + wm + mf * 16 + lq;
        #pragma unroll
        for (int nf = 0; nf < 8; nf++) {
            int col = nblk + wn + nf * 8 + lr * 2;
            float b0 = __ldg(bias + col);
            float b1 = __ldg(bias + col + 1);
            float2 v0 = make_float2(acc[mf][nf][0] + b0, acc[mf][nf][1] + b1);
            float2 v1 = make_float2(acc[mf][nf][2] + b0, acc[mf][nf][3] + b1);
            *reinterpret_cast<float2*>(C + row * (size_t)N + col)       = v0;
            *reinterpret_cast<float2*>(C + (row + 8) * (size_t)N + col) = v1;
        }
    }
}

// ======================= fused attention =======================
// Writes g_att as tf32-rounded bits (numerically identical to GEMM2's old A-cvt).
__global__ void __launch_bounds__(128)
attn_kernel(const float* __restrict__ bias_table)
{
    __shared__ float sQ[4][TT][33];
    __shared__ float sK[4][TT][33];
    __shared__ float sV[4][TT][33];
    __shared__ float sP[4][TT * TT];
    __shared__ float sB[(2 * TT - 1) * NH];

    const int w    = threadIdx.x >> 5;
    const int lane = threadIdx.x & 31;

    for (int i = threadIdx.x; i < (2 * TT - 1) * NH; i += 128)
        sB[i] = bias_table[i];

    const int unit = blockIdx.x * 4 + w;
    const int b = unit / NH;
    const int h = unit - b * NH;

    const float* base = g_qkv + (size_t)(b * TT) * NQKV + h * DH;

    __syncthreads();

    #pragma unroll
    for (int t = 0; t < TT; t++) {
        sQ[w][t][lane] = base[t * NQKV + lane];
        sK[w][t][lane] = base[t * NQKV + DIM + lane];
        sV[w][t][lane] = base[t * NQKV + 2 * DIM + lane];
    }
    __syncwarp();

    const float scale = 0.17677669529663687f;
    for (int e = lane; e < TT * TT; e += 32) {
        int t = e / TT;
        int j = e - t * TT;
        float a = 0.0f;
        #pragma unroll
        for (int d = 0; d < DH; d++)
            a += sQ[w][t][d] * sK[w][j][d];
        sP[w][e] = a * scale + sB[(t - j + TT - 1) * NH + h];
    }
    __syncwarp();

    if (lane < TT) {
        float row[TT];
        float m = -1e30f;
        #pragma unroll
        for (int j = 0; j < TT; j++) { row[j] = sP[w][lane * TT + j]; m = fmaxf(m, row[j]); }
        float s = 0.0f;
        #pragma unroll
        for (int j = 0; j < TT; j++) { row[j] = __expf(row[j] - m); s += row[j]; }
        float inv = 1.0f / s;
        #pragma unroll
        for (int j = 0; j < TT; j++) sP[w][lane * TT + j] = row[j] * inv;
    }
    __syncwarp();

    float* outp = g_att + (size_t)(b * TT) * DIM + h * DH;
    #pragma unroll
    for (int t = 0; t < TT; t++) {
        float a = 0.0f;
        #pragma unroll
        for (int j = 0; j < TT; j++)
            a += sP[w][t * TT + j] * sV[w][j][lane];
        outp[t * DIM + lane] = __uint_as_float(f2tf(a));   // tf32 bits for GEMM2
    }
}

extern "C" void kernel_launch(void* const* d_in, const int* in_sizes, int n_in,
                              void* d_out, int out_size)
{
    (void)in_sizes; (void)n_in; (void)out_size;
    const float* x      = (const float*)d_in[0];   // [16384,10,384]
    const float* qkv_w  = (const float*)d_in[1];   // [1152,384]
    const float* qkv_b  = (const float*)d_in[2];   // [1152]
    const float* proj_w = (const float*)d_in[3];   // [384,384]
    const float* proj_b = (const float*)d_in[4];   // [384]
    const float* bias_t = (const float*)d_in[5];   // [19,12]
    float* out = (float*)d_out;                    // [163840,384]

    void* pq = nullptr; void* pa = nullptr;
    void* pwq = nullptr; void* pwp = nullptr;
    cudaGetSymbolAddress(&pq, g_qkv);
    cudaGetSymbolAddress(&pa, g_att);
    cudaGetSymbolAddress(&pwq, g_wq);
    cudaGetSymbolAddress(&pwp, g_wp);

    const int smem_bytes = NSTAGE * (int)STAGE_BYTES;   // 110592
    cudaFuncSetAttribute(gemm_tf32<true>,  cudaFuncAttributeMaxDynamicSharedMemorySize, smem_bytes);
    cudaFuncSetAttribute(gemm_tf32<false>, cudaFuncAttributeMaxDynamicSharedMemorySize, smem_bytes);

    // 0) Pre-convert weights to tf32 bits
    const int nconv = (NQKV * KDIM + DIM * KDIM) / 4;
    conv_w<<<(nconv + 255) / 256, 256>>>(qkv_w, proj_w);

    // 1) qkv = x @ qkv_w^T + qkv_b   (A = raw fp32 -> cvt in-loop)
    dim3 g1(NQKV / 128, MROWS / 128);   // (9, 1280)
    gemm_tf32<true><<<g1, 128, smem_bytes>>>(x, (const uint32_t*)pwq, qkv_b, (float*)pq, NQKV);

    // 2) attention, one warp per (b, h); writes tf32 bits
    attn_kernel<<<(NB * NH) / 4, 128>>>(bias_t);

    // 3) out = att @ proj_w^T + proj_b   (A already tf32 bits)
    dim3 g2(DIM / 128, MROWS / 128);    // (3, 1280)
    gemm_tf32<false><<<g2, 128, smem_bytes>>>((const float*)pa, (const uint32_t*)pwp, proj_b, out, DIM);
}